// round 15
// baseline (speedup 1.0000x reference)
#include <cuda_runtime.h>
#include <math.h>
#include <stdint.h>

#define B_   32
#define T_   512
#define E_   256
#define H_   512
#define NG   2048
#define NBLK 128

typedef unsigned long long u64;

__device__ __align__(16) float  g_xWx  [(size_t)T_ * B_ * NG];
__device__ __align__(16) float  g_fcore[(size_t)T_ * B_ * 192];
__device__ __align__(16) float  g_revxw[(size_t)T_ * B_ * 40];
__device__ __align__(16) float2 g_d    [T_ * B_];
__device__ __align__(16) float  g_h    [2][B_ * H_];
__device__ unsigned g_cnt;                               // monotonic arrival counter
__device__ __align__(128) unsigned g_genv[NBLK * 32];    // per-block gen flags, 128B apart

__device__ __forceinline__ float sigf(float x) { return 1.f / (1.f + expf(-x)); }

// ---- packed f32x2 helpers ----
__device__ __forceinline__ u64 ffma2(u64 a, u64 b, u64 c) {
    u64 d;
    asm("fma.rn.f32x2 %0, %1, %2, %3;" : "=l"(d) : "l"(a), "l"(b), "l"(c));
    return d;
}
__device__ __forceinline__ u64 dup2(float x) {
    u64 r; asm("mov.b64 %0, {%1, %1};" : "=l"(r) : "f"(x)); return r;
}
__device__ __forceinline__ u64 pack2(float lo, float hi) {
    u64 r; asm("mov.b64 %0, {%1, %2};" : "=l"(r) : "f"(lo), "f"(hi)); return r;
}
__device__ __forceinline__ float2 lohi(u64 v) {
    float2 r; asm("mov.b64 {%0, %1}, %2;" : "=f"(r.x), "=f"(r.y) : "l"(v)); return r;
}

// ---- memory-model primitives ----
__device__ __forceinline__ unsigned atom_add_acqrel(unsigned* p, unsigned v) {
    unsigned old;
    asm volatile("atom.acq_rel.gpu.global.add.u32 %0, [%1], %2;"
                 : "=r"(old) : "l"(p), "r"(v) : "memory");
    return old;
}
__device__ __forceinline__ void st_release(unsigned* p, unsigned v) {
    asm volatile("st.release.gpu.global.u32 [%0], %1;" :: "l"(p), "r"(v) : "memory");
}
__device__ __forceinline__ unsigned ld_acquire(const unsigned* p) {
    unsigned v;
    asm volatile("ld.acquire.gpu.global.u32 %0, [%1];" : "=r"(v) : "l"(p) : "memory");
    return v;
}

// =================== fused pre-kernel: xwx (2048) | conv (1024) | revxw (512) ===================
__global__ void __launch_bounds__(256) k_pre(const float* __restrict__ x,
        const float* __restrict__ cWx, const float* __restrict__ cbias,
        const float* __restrict__ w1, const float* __restrict__ b1,
        const float* __restrict__ w2, const float* __restrict__ b2,
        const float* __restrict__ w3, const float* __restrict__ b3,
        const float* __restrict__ rWx)
{
    __shared__ __align__(16) float buf[8192];
    const int bid = blockIdx.x;
    const int tid = threadIdx.x;

    if (bid < 2048) {
        // ---------- xWx GEMM ----------
        float (*a_sh)[128] = (float(*)[128])buf;
        float (*b_sh)[128] = (float(*)[128])(buf + 1024);
        const int n0 = (bid & 15) * 128;
        const int m0 = (bid >> 4) * 128;
        const int ty8 = (tid >> 4) * 8;
        const int tx8 = (tid & 15) * 8;

        u64 acc[8][4];
#pragma unroll
        for (int i = 0; i < 8; ++i)
#pragma unroll
            for (int j = 0; j < 4; ++j) acc[i][j] = 0ull;

        const int arow = tid >> 1;
        const int akq  = (tid & 1) * 4;
        const int m    = m0 + arow;
        const int bb   = m & 31;
        const int tt   = m >> 5;
        const float* aptr = x + ((size_t)bb * T_ + tt) * E_ + akq;
        const int bkk = tid >> 5;
        const int bnq = (tid & 31) * 4;

        for (int k0 = 0; k0 < E_; k0 += 8) {
            float4 av = *(const float4*)(aptr + k0);
            a_sh[akq + 0][arow] = av.x;
            a_sh[akq + 1][arow] = av.y;
            a_sh[akq + 2][arow] = av.z;
            a_sh[akq + 3][arow] = av.w;
            *(float4*)&b_sh[bkk][bnq] = *(const float4*)(cWx + (size_t)(k0 + bkk) * NG + n0 + bnq);
            __syncthreads();
#pragma unroll
            for (int k = 0; k < 8; ++k) {
                float af[8];
                *(float4*)(af)     = *(const float4*)&a_sh[k][ty8];
                *(float4*)(af + 4) = *(const float4*)&a_sh[k][ty8 + 4];
                ulonglong2 b01 = *(const ulonglong2*)&b_sh[k][tx8];
                ulonglong2 b23 = *(const ulonglong2*)&b_sh[k][tx8 + 4];
#pragma unroll
                for (int i = 0; i < 8; ++i) {
                    u64 ai = dup2(af[i]);
                    acc[i][0] = ffma2(ai, b01.x, acc[i][0]);
                    acc[i][1] = ffma2(ai, b01.y, acc[i][1]);
                    acc[i][2] = ffma2(ai, b23.x, acc[i][2]);
                    acc[i][3] = ffma2(ai, b23.y, acc[i][3]);
                }
            }
            __syncthreads();
        }
        float bsv[8];
        *(float4*)(bsv)     = *(const float4*)(cbias + n0 + tx8);
        *(float4*)(bsv + 4) = *(const float4*)(cbias + n0 + tx8 + 4);
#pragma unroll
        for (int i = 0; i < 8; ++i) {
            float* cp = g_xWx + (size_t)(m0 + ty8 + i) * NG + n0 + tx8;
            float2 p0 = lohi(acc[i][0]), p1 = lohi(acc[i][1]);
            float2 p2 = lohi(acc[i][2]), p3 = lohi(acc[i][3]);
            *(float4*)cp       = make_float4(p0.x + bsv[0], p0.y + bsv[1], p1.x + bsv[2], p1.y + bsv[3]);
            *(float4*)(cp + 4) = make_float4(p2.x + bsv[4], p2.y + bsv[5], p3.x + bsv[6], p3.y + bsv[7]);
        }
    } else if (bid < 3072) {
        // ---------- convs: 16 timesteps per block, 4 t per thread ----------
        float (*xs)[256] = (float(*)[256])buf;
        const int cb = bid - 2048;
        const int t0 = (cb & 31) * 16;
        const int b  = cb >> 5;

        for (int i = tid; i < 20 * 256; i += 256) {
            int r = i >> 8, e = i & 255;
            int t = t0 - 2 + r;
            xs[r][e] = (t >= 0 && t < T_) ? x[((size_t)b * T_ + t) * E_ + e] : 0.f;
        }
        __syncthreads();
        if (tid >= 180) return;

        const int tq  = tid / 45;
        const int grp = tid % 45;
        const float* w; const float* bias; int K, pl, cbase, c4;
        if (grp < 15)      { w = w1; bias = b1; K = 3; pl = 1; cbase = 0;   c4 = grp * 4; }
        else if (grp < 30) { w = w2; bias = b2; K = 4; pl = 1; cbase = 60;  c4 = (grp - 15) * 4; }
        else               { w = w3; bias = b3; K = 5; pl = 2; cbase = 120; c4 = (grp - 30) * 4; }

        u64 a01[4], a23[4];
        u64 bi01 = pack2(bias[c4], bias[c4 + 1]);
        u64 bi23 = pack2(bias[c4 + 2], bias[c4 + 3]);
#pragma unroll
        for (int i = 0; i < 4; ++i) { a01[i] = bi01; a23[i] = bi23; }

        for (int dt = 0; dt < K; ++dt) {
            const int rb = tq * 4 + dt - pl + 2;
            const float* wp = w + (size_t)dt * E_ * 60 + c4;
#pragma unroll 2
            for (int e = 0; e < E_; ++e) {
                ulonglong2 wv = *(const ulonglong2*)(wp + (size_t)e * 60);
#pragma unroll
                for (int i = 0; i < 4; ++i) {
                    u64 xd = dup2(xs[rb + i][e]);
                    a01[i] = ffma2(xd, wv.x, a01[i]);
                    a23[i] = ffma2(xd, wv.y, a23[i]);
                }
            }
        }
#pragma unroll
        for (int i = 0; i < 4; ++i) {
            const int t = t0 + tq * 4 + i;
            float2 p0 = lohi(a01[i]), p1 = lohi(a23[i]);
            *(float4*)&g_fcore[((size_t)t * B_ + b) * 192 + cbase + c4] =
                make_float4(p0.x, p0.y, p1.x, p1.y);
        }
    } else {
        // ---------- rev-LSTM input projection ----------
        float (*xr)[256] = (float(*)[256])buf;
        const int s = bid - 3072;
        const int t = T_ - 1 - s;
        for (int i = tid; i < 32 * 256; i += 256) {
            int b = i >> 8, e = i & 255;
            xr[b][e] = x[((size_t)b * T_ + t) * E_ + e];
        }
        __syncthreads();
#pragma unroll
        for (int pass = 0; pass < 2; ++pass) {
            int jj = tid + pass * 256;
            if (jj >= 320) break;
            const int b = jj / 10, j = jj % 10;
            float a0 = 0.f, a1 = 0.f, a2 = 0.f, a3 = 0.f;
#pragma unroll 4
            for (int e = 0; e < 256; ++e) {
                float xv = xr[b][e];
                const float* wp = rWx + (size_t)e * 40 + j;
                a0 = fmaf(xv, __ldg(wp),      a0);
                a1 = fmaf(xv, __ldg(wp + 10), a1);
                a2 = fmaf(xv, __ldg(wp + 20), a2);
                a3 = fmaf(xv, __ldg(wp + 30), a3);
            }
            float* dst = &g_revxw[((size_t)s * B_ + b) * 40 + j];
            dst[0] = a0; dst[10] = a1; dst[20] = a2; dst[30] = a3;
        }
    }
}

// ------------------- rev-LSTM scan: 32 independent warps, shfl exchange -------------------
__global__ void __launch_bounds__(32) k_revscan(const float* __restrict__ Wh,
                                                const float* __restrict__ bias)
{
    const int b = blockIdx.x;
    const int j = threadIdx.x;
    const bool act = (j < 10);

    float w[10][4];
    float bz0 = 0.f, bz1 = 0.f, bz2 = 0.f, bz3 = 0.f;
#pragma unroll
    for (int p = 0; p < 10; ++p)
#pragma unroll
        for (int g = 0; g < 4; ++g)
            w[p][g] = act ? __ldg(Wh + p * 40 + g * 10 + j) : 0.f;
    if (act) {
        bz0 = __ldg(bias + j);
        bz1 = __ldg(bias + 10 + j);
        bz2 = __ldg(bias + 20 + j);
        bz3 = __ldg(bias + 30 + j);
    }

    float h = 0.f, c = 0.f;
    float4 z = make_float4(0.f, 0.f, 0.f, 0.f);
    if (act) {
        const float* zp = g_revxw + (size_t)b * 40;
        z = make_float4(__ldg(zp + j), __ldg(zp + 10 + j),
                        __ldg(zp + 20 + j), __ldg(zp + 30 + j));
    }

    for (int s = 0; s < T_; ++s) {
        float4 zn = make_float4(0.f, 0.f, 0.f, 0.f);
        if (act && s + 1 < T_) {
            const float* zp = g_revxw + ((size_t)(s + 1) * B_ + b) * 40;
            zn = make_float4(__ldg(zp + j), __ldg(zp + 10 + j),
                             __ldg(zp + 20 + j), __ldg(zp + 30 + j));
        }
        float zi = z.x + bz0, zf = z.y + bz1, zg = z.z + bz2, zo = z.w + bz3;
#pragma unroll
        for (int p = 0; p < 10; ++p) {
            float hp = __shfl_sync(0xffffffffu, h, p);
            zi = fmaf(hp, w[p][0], zi);
            zf = fmaf(hp, w[p][1], zf);
            zg = fmaf(hp, w[p][2], zg);
            zo = fmaf(hp, w[p][3], zo);
        }
        c = sigf(zf) * c + sigf(zi) * tanhf(zg);
        h = sigf(zo) * tanhf(c);
        if (act) g_fcore[((size_t)s * B_ + b) * 192 + 180 + j] = h;
        z = zn;
    }
}

// ------------------- gate MLP (+ h/barrier init folded in) -------------------
__global__ void __launch_bounds__(128) k_gate(const float* __restrict__ x,
        const float* __restrict__ d0W, const float* __restrict__ d0b,
        const float* __restrict__ d1W, const float* __restrict__ d1b,
        const float* __restrict__ gn)
{
    __shared__ float in_sh[8][448];
    __shared__ float hid_sh[8][100];
    const int q0 = blockIdx.x * 8;
    const int tid = threadIdx.x;

    if (blockIdx.x < 8) {
        float* hz = &g_h[0][blockIdx.x * 2048];
        for (int i = tid; i < 2048; i += 128) hz[i] = 0.f;
        if (blockIdx.x == 0) {
            if (tid < 128) g_genv[tid * 32] = 0u;    // reset private gen flags
            if (tid == 0) g_cnt = 0u;                // reset monotonic counter
        }
    }

    for (int i = tid; i < 8 * 448; i += 128) {
        int u = i / 448, e = i % 448;
        int q = q0 + u, t = q >> 5, b = q & 31;
        float v = 0.f;
        if (e < 190) { if (t < T_ - 1) v = g_fcore[((size_t)(t + 1) * B_ + b) * 192 + e]; }
        else if (e < 446) v = x[((size_t)b * T_ + t) * E_ + (e - 190)];
        in_sh[u][e] = v;
    }
    __syncthreads();
    if (tid < 100) {
        float acc[8];
#pragma unroll
        for (int u = 0; u < 8; ++u) acc[u] = d0b[tid];
        for (int e = 0; e < 446; ++e) {
            float w = d0W[(size_t)e * 100 + tid];
#pragma unroll
            for (int u = 0; u < 8; ++u) acc[u] = fmaf(in_sh[u][e], w, acc[u]);
        }
#pragma unroll
        for (int u = 0; u < 8; ++u) hid_sh[u][tid] = fmaxf(acc[u], 0.f);
    }
    __syncthreads();
    if (tid < 8) {
        const int u = tid, q = q0 + u, t = q >> 5, b = q & 31;
        float p0 = d1b[0], p1 = d1b[1];
        for (int j = 0; j < 100; ++j) {
            float hv = hid_sh[u][j];
            p0 = fmaf(hv, d1W[2 * j],     p0);
            p1 = fmaf(hv, d1W[2 * j + 1], p1);
        }
        float a0 = (p0 + gn[((size_t)t * B_ + b) * 2])     / 1e-5f;
        float a1 = (p1 + gn[((size_t)t * B_ + b) * 2 + 1]) / 1e-5f;
        float mx = fmaxf(a0, a1);
        float e0 = expf(a0 - mx), e1 = expf(a1 - mx);
        float s = e0 + e1;
        g_d[q] = make_float2(e0 / s, e1 / s);
    }
}

// ------------------- main persistent scan: R11 body + broadcast-release barrier -------------------
__global__ void __launch_bounds__(256, 1) k_scan(const float* __restrict__ Wh,
                                                 float* __restrict__ out)
{
    extern __shared__ float sm[];
    float* h_sh    = sm;               // [32][512]  64KB
    float* part_sh = sm + 32 * 512;    // [8][512]   16KB
    const int tid  = threadIdx.x;
    const int nb   = blockIdx.x;
    const int wid  = tid >> 5;
    const int lane = tid & 31;
    const int kc    = lane >> 4;
    const int c_idx = lane & 15;
    const int k0    = wid * 64 + kc * 32;
    const int ncol  = (c_idx >> 2) * 512 + nb * 4 + (c_idx & 3);
    const int rot   = nb & 3;

    u64 wreg[16];
#pragma unroll
    for (int j = 0; j < 16; ++j) {
        float w0 = __ldg(Wh + (size_t)(k0 + 2 * j)     * NG + ncol);
        float w1 = __ldg(Wh + (size_t)(k0 + 2 * j + 1) * NG + ncol);
        wreg[j] = pack2(w0, w1);
    }

    const int cb = tid >> 2;
    const int hh = tid & 3;
    const int hglob = nb * 4 + hh;
    float cst = 0.f;

    // prologue prefetch for t=0
    float4 zx = make_float4(0.f, 0.f, 0.f, 0.f);
    float2 dv = make_float2(0.f, 0.f);
    if (tid < 128) {
        const float* xw = g_xWx + ((size_t)cb) * NG + hglob;
        zx.x = __ldg(xw);
        zx.y = __ldg(xw + 512);
        zx.z = __ldg(xw + 1024);
        zx.w = __ldg(xw + 1536);
        dv = g_d[cb];
    }

    for (int t = 0; t < T_; ++t) {
        const int cur = t & 1;
        const float4* hg4 = (const float4*)g_h[cur];

        // stage chunk 0 (rotated by nb to de-hotspot L2)
        float4 pre[4];
        {
            const int base0 = rot * 1024 + tid;
#pragma unroll
            for (int q = 0; q < 4; ++q) pre[q] = __ldcg(hg4 + base0 + q * 256);
#pragma unroll
            for (int q = 0; q < 4; ++q) ((float4*)h_sh)[base0 + q * 256] = pre[q];
        }

        // prefetch NEXT step's xw/d
        float4 zxn; float2 dvn;
        if (tid < 128 && t + 1 < T_) {
            const float* xwn = g_xWx + ((size_t)(t + 1) * B_ + cb) * NG + hglob;
            zxn.x = __ldg(xwn);
            zxn.y = __ldg(xwn + 512);
            zxn.z = __ldg(xwn + 1024);
            zxn.w = __ldg(xwn + 1536);
            dvn = g_d[(t + 1) * B_ + cb];
        }
        __syncthreads();

        // ---- chunk-pipelined dot (R11 layout) ----
        u64 acc2[32];
#pragma unroll
        for (int i = 0; i < 32; ++i) acc2[i] = 0ull;
#pragma unroll
        for (int cc = 0; cc < 4; ++cc) {
            const int ch = (cc + rot) & 3;
            if (cc < 3) {
                const int basen = (((cc + 1 + rot) & 3)) * 1024 + tid;
#pragma unroll
                for (int q = 0; q < 4; ++q) pre[q] = __ldcg(hg4 + basen + q * 256);
            }
            const float* hbase = h_sh + (ch * 8) * 512 + k0;
#pragma unroll
            for (int bb = 0; bb < 8; ++bb) {
                const ulonglong2* hp = (const ulonglong2*)(hbase + bb * 512);
                u64 a = acc2[cc * 8 + bb];
#pragma unroll
                for (int q = 0; q < 4; ++q) {
                    ulonglong2 h01 = hp[2 * q];
                    ulonglong2 h23 = hp[2 * q + 1];
                    a = ffma2(h01.x, wreg[4 * q + 0], a);
                    a = ffma2(h01.y, wreg[4 * q + 1], a);
                    a = ffma2(h23.x, wreg[4 * q + 2], a);
                    a = ffma2(h23.y, wreg[4 * q + 3], a);
                }
                acc2[cc * 8 + bb] = a;
            }
            if (cc < 3) {
                const int basen = (((cc + 1 + rot) & 3)) * 1024 + tid;
#pragma unroll
                for (int q = 0; q < 4; ++q) ((float4*)h_sh)[basen + q * 256] = pre[q];
                __syncthreads();
            }
        }

        // ---- reduce ----
#pragma unroll
        for (int idx = 0; idx < 32; ++idx) {
            float2 p = lohi(acc2[idx]);
            float v = p.x + p.y;
            v += __shfl_xor_sync(0xffffffffu, v, 16);
            if (kc == 0) {
                int realb = (((idx >> 3) + rot) & 3) * 8 + (idx & 7);
                part_sh[wid * 512 + realb * 16 + c_idx] = v;
            }
        }
        __syncthreads();

        if (tid < 128) {
            float zg4[4];
#pragma unroll
            for (int g = 0; g < 4; ++g) {
                float s = 0.f;
#pragma unroll
                for (int w8 = 0; w8 < 8; ++w8)
                    s += part_sh[w8 * 512 + cb * 16 + g * 4 + hh];
                zg4[g] = s;
            }
            float zi = zg4[0] + zx.x;
            float zf = zg4[1] + zx.y;
            float zg = zg4[2] + zx.z;
            float zo = zg4[3] + zx.w;
            float ccand = sigf(zf) * cst + sigf(zi) * tanhf(zg);
            float hcand = sigf(zo) * tanhf(ccand);
            float hold = h_sh[cb * 512 + hglob];
            float hnew = dv.x * hcand + dv.y * hold;
            cst = dv.x * ccand + dv.y * cst;
            g_h[1 - cur][cb * 512 + hglob] = hnew;
            out[(size_t)cb * (T_ * H_) + (size_t)t * H_ + hglob] = hcand;
            zx = zxn; dv = dvn;
        }
        __syncthreads();

        // ---- broadcast-release barrier ----
        // arrival: monotonic acq_rel counter (no reset). release: last block's warp 0
        // fans out t+1 to 128 private flag lines; each block polls ONLY its own line.
        if (wid == 0) {
            unsigned last = 0;
            if (lane == 0) {
                unsigned a = atom_add_acqrel(&g_cnt, 1u);
                last = (a == (unsigned)(t + 1) * NBLK - 1u) ? 1u : 0u;
            }
            last = __shfl_sync(0xffffffffu, last, 0);
            if (last) {
#pragma unroll
                for (int q = 0; q < 4; ++q)
                    st_release(&g_genv[(lane * 4 + q) * 32], (unsigned)(t + 1));
            } else if (lane == 0) {
                while (ld_acquire(&g_genv[nb * 32]) < (unsigned)(t + 1)) __nanosleep(8);
            }
        }
        __syncthreads();
    }
}

extern "C" void kernel_launch(void* const* d_in, const int* in_sizes, int n_in,
                              void* d_out, int out_size) {
    const float* x   = (const float*)d_in[0];
    const float* c1w = (const float*)d_in[1];
    const float* c1b = (const float*)d_in[2];
    const float* c2w = (const float*)d_in[3];
    const float* c2b = (const float*)d_in[4];
    const float* c3w = (const float*)d_in[5];
    const float* c3b = (const float*)d_in[6];
    const float* rWx = (const float*)d_in[7];
    const float* rWh = (const float*)d_in[8];
    const float* rb  = (const float*)d_in[9];
    const float* d0W = (const float*)d_in[10];
    const float* d0b = (const float*)d_in[11];
    const float* d1W = (const float*)d_in[12];
    const float* d1b = (const float*)d_in[13];
    const float* cWx = (const float*)d_in[14];
    const float* cWh = (const float*)d_in[15];
    const float* cb  = (const float*)d_in[16];
    const float* gn  = (const float*)d_in[17];
    float* out = (float*)d_out;

    static int smem_set = 0;
    const int SMEM = (32 * 512 + 8 * 512) * 4;   // 80 KB
    if (!smem_set) {
        cudaFuncSetAttribute(k_scan, cudaFuncAttributeMaxDynamicSharedMemorySize, SMEM);
        smem_set = 1;
    }

    k_pre<<<3584, 256>>>(x, cWx, cb, c1w, c1b, c2w, c2b, c3w, c3b, rWx);
    k_revscan<<<32, 32>>>(rWh, rb);
    k_gate<<<(T_ * B_) / 8, 128>>>(x, d0W, d0b, d1W, d1b, gn);
    k_scan<<<NBLK, 256, SMEM>>>(cWh, out);
}

// round 16
// speedup vs baseline: 1.2258x; 1.2258x over previous
#include <cuda_runtime.h>
#include <math.h>
#include <stdint.h>

#define B_   32
#define T_   512
#define E_   256
#define H_   512
#define NG   2048
#define NWORK 128
#define NBLK  152

typedef unsigned long long u64;

__device__ __align__(16) float  g_xWx  [(size_t)T_ * B_ * NG];
__device__ __align__(16) float  g_fcore[(size_t)T_ * B_ * 192];
__device__ __align__(16) float  g_revxw[(size_t)T_ * B_ * 40];
__device__ __align__(16) float2 g_d    [T_ * B_];
__device__ __align__(16) float  g_h    [2][B_ * H_];
__device__ unsigned g_cnt;
__device__ unsigned g_gen;

__device__ __forceinline__ float sigf(float x) { return 1.f / (1.f + expf(-x)); }

// ---- packed f32x2 helpers ----
__device__ __forceinline__ u64 ffma2(u64 a, u64 b, u64 c) {
    u64 d;
    asm("fma.rn.f32x2 %0, %1, %2, %3;" : "=l"(d) : "l"(a), "l"(b), "l"(c));
    return d;
}
__device__ __forceinline__ u64 dup2(float x) {
    u64 r; asm("mov.b64 %0, {%1, %1};" : "=l"(r) : "f"(x)); return r;
}
__device__ __forceinline__ u64 pack2(float lo, float hi) {
    u64 r; asm("mov.b64 %0, {%1, %2};" : "=l"(r) : "f"(lo), "f"(hi)); return r;
}
__device__ __forceinline__ float2 lohi(u64 v) {
    float2 r; asm("mov.b64 {%0, %1}, %2;" : "=f"(r.x), "=f"(r.y) : "l"(v)); return r;
}

// ---- release/acquire primitives ----
__device__ __forceinline__ unsigned atom_add_release(unsigned* p, unsigned v) {
    unsigned old;
    asm volatile("atom.release.gpu.global.add.u32 %0, [%1], %2;"
                 : "=r"(old) : "l"(p), "r"(v) : "memory");
    return old;
}
__device__ __forceinline__ void st_release(unsigned* p, unsigned v) {
    asm volatile("st.release.gpu.global.u32 [%0], %1;" :: "l"(p), "r"(v) : "memory");
}
__device__ __forceinline__ unsigned ld_acquire(const unsigned* p) {
    unsigned v;
    asm volatile("ld.acquire.gpu.global.u32 %0, [%1];" : "=r"(v) : "l"(p) : "memory");
    return v;
}

// =================== fused pre-kernel: xwx (2048) | conv (1024) | revxw (512) ===================
__global__ void __launch_bounds__(256) k_pre(const float* __restrict__ x,
        const float* __restrict__ cWx, const float* __restrict__ cbias,
        const float* __restrict__ w1, const float* __restrict__ b1,
        const float* __restrict__ w2, const float* __restrict__ b2,
        const float* __restrict__ w3, const float* __restrict__ b3,
        const float* __restrict__ rWx)
{
    __shared__ __align__(16) float buf[8192];
    const int bid = blockIdx.x;
    const int tid = threadIdx.x;

    if (bid < 2048) {
        // ---------- xWx GEMM ----------
        float (*a_sh)[128] = (float(*)[128])buf;
        float (*b_sh)[128] = (float(*)[128])(buf + 1024);
        const int n0 = (bid & 15) * 128;
        const int m0 = (bid >> 4) * 128;
        const int ty8 = (tid >> 4) * 8;
        const int tx8 = (tid & 15) * 8;

        u64 acc[8][4];
#pragma unroll
        for (int i = 0; i < 8; ++i)
#pragma unroll
            for (int j = 0; j < 4; ++j) acc[i][j] = 0ull;

        const int arow = tid >> 1;
        const int akq  = (tid & 1) * 4;
        const int m    = m0 + arow;
        const int bb   = m & 31;
        const int tt   = m >> 5;
        const float* aptr = x + ((size_t)bb * T_ + tt) * E_ + akq;
        const int bkk = tid >> 5;
        const int bnq = (tid & 31) * 4;

        for (int k0 = 0; k0 < E_; k0 += 8) {
            float4 av = *(const float4*)(aptr + k0);
            a_sh[akq + 0][arow] = av.x;
            a_sh[akq + 1][arow] = av.y;
            a_sh[akq + 2][arow] = av.z;
            a_sh[akq + 3][arow] = av.w;
            *(float4*)&b_sh[bkk][bnq] = *(const float4*)(cWx + (size_t)(k0 + bkk) * NG + n0 + bnq);
            __syncthreads();
#pragma unroll
            for (int k = 0; k < 8; ++k) {
                float af[8];
                *(float4*)(af)     = *(const float4*)&a_sh[k][ty8];
                *(float4*)(af + 4) = *(const float4*)&a_sh[k][ty8 + 4];
                ulonglong2 b01 = *(const ulonglong2*)&b_sh[k][tx8];
                ulonglong2 b23 = *(const ulonglong2*)&b_sh[k][tx8 + 4];
#pragma unroll
                for (int i = 0; i < 8; ++i) {
                    u64 ai = dup2(af[i]);
                    acc[i][0] = ffma2(ai, b01.x, acc[i][0]);
                    acc[i][1] = ffma2(ai, b01.y, acc[i][1]);
                    acc[i][2] = ffma2(ai, b23.x, acc[i][2]);
                    acc[i][3] = ffma2(ai, b23.y, acc[i][3]);
                }
            }
            __syncthreads();
        }
        float bsv[8];
        *(float4*)(bsv)     = *(const float4*)(cbias + n0 + tx8);
        *(float4*)(bsv + 4) = *(const float4*)(cbias + n0 + tx8 + 4);
#pragma unroll
        for (int i = 0; i < 8; ++i) {
            float* cp = g_xWx + (size_t)(m0 + ty8 + i) * NG + n0 + tx8;
            float2 p0 = lohi(acc[i][0]), p1 = lohi(acc[i][1]);
            float2 p2 = lohi(acc[i][2]), p3 = lohi(acc[i][3]);
            *(float4*)cp       = make_float4(p0.x + bsv[0], p0.y + bsv[1], p1.x + bsv[2], p1.y + bsv[3]);
            *(float4*)(cp + 4) = make_float4(p2.x + bsv[4], p2.y + bsv[5], p3.x + bsv[6], p3.y + bsv[7]);
        }
    } else if (bid < 3072) {
        // ---------- convs: 16 timesteps per block, 4 t per thread ----------
        float (*xs)[256] = (float(*)[256])buf;
        const int cb = bid - 2048;
        const int t0 = (cb & 31) * 16;
        const int b  = cb >> 5;

        for (int i = tid; i < 20 * 256; i += 256) {
            int r = i >> 8, e = i & 255;
            int t = t0 - 2 + r;
            xs[r][e] = (t >= 0 && t < T_) ? x[((size_t)b * T_ + t) * E_ + e] : 0.f;
        }
        __syncthreads();
        if (tid >= 180) return;

        const int tq  = tid / 45;
        const int grp = tid % 45;
        const float* w; const float* bias; int K, pl, cbase, c4;
        if (grp < 15)      { w = w1; bias = b1; K = 3; pl = 1; cbase = 0;   c4 = grp * 4; }
        else if (grp < 30) { w = w2; bias = b2; K = 4; pl = 1; cbase = 60;  c4 = (grp - 15) * 4; }
        else               { w = w3; bias = b3; K = 5; pl = 2; cbase = 120; c4 = (grp - 30) * 4; }

        u64 a01[4], a23[4];
        u64 bi01 = pack2(bias[c4], bias[c4 + 1]);
        u64 bi23 = pack2(bias[c4 + 2], bias[c4 + 3]);
#pragma unroll
        for (int i = 0; i < 4; ++i) { a01[i] = bi01; a23[i] = bi23; }

        for (int dt = 0; dt < K; ++dt) {
            const int rb = tq * 4 + dt - pl + 2;
            const float* wp = w + (size_t)dt * E_ * 60 + c4;
#pragma unroll 2
            for (int e = 0; e < E_; ++e) {
                ulonglong2 wv = *(const ulonglong2*)(wp + (size_t)e * 60);
#pragma unroll
                for (int i = 0; i < 4; ++i) {
                    u64 xd = dup2(xs[rb + i][e]);
                    a01[i] = ffma2(xd, wv.x, a01[i]);
                    a23[i] = ffma2(xd, wv.y, a23[i]);
                }
            }
        }
#pragma unroll
        for (int i = 0; i < 4; ++i) {
            const int t = t0 + tq * 4 + i;
            float2 p0 = lohi(a01[i]), p1 = lohi(a23[i]);
            *(float4*)&g_fcore[((size_t)t * B_ + b) * 192 + cbase + c4] =
                make_float4(p0.x, p0.y, p1.x, p1.y);
        }
    } else {
        // ---------- rev-LSTM input projection ----------
        float (*xr)[256] = (float(*)[256])buf;
        const int s = bid - 3072;
        const int t = T_ - 1 - s;
        for (int i = tid; i < 32 * 256; i += 256) {
            int b = i >> 8, e = i & 255;
            xr[b][e] = x[((size_t)b * T_ + t) * E_ + e];
        }
        __syncthreads();
#pragma unroll
        for (int pass = 0; pass < 2; ++pass) {
            int jj = tid + pass * 256;
            if (jj >= 320) break;
            const int b = jj / 10, j = jj % 10;
            float a0 = 0.f, a1 = 0.f, a2 = 0.f, a3 = 0.f;
#pragma unroll 4
            for (int e = 0; e < 256; ++e) {
                float xv = xr[b][e];
                const float* wp = rWx + (size_t)e * 40 + j;
                a0 = fmaf(xv, __ldg(wp),      a0);
                a1 = fmaf(xv, __ldg(wp + 10), a1);
                a2 = fmaf(xv, __ldg(wp + 20), a2);
                a3 = fmaf(xv, __ldg(wp + 30), a3);
            }
            float* dst = &g_revxw[((size_t)s * B_ + b) * 40 + j];
            dst[0] = a0; dst[10] = a1; dst[20] = a2; dst[30] = a3;
        }
    }
}

// ------------------- rev-LSTM scan: 32 independent warps, shfl exchange -------------------
__global__ void __launch_bounds__(32) k_revscan(const float* __restrict__ Wh,
                                                const float* __restrict__ bias)
{
    const int b = blockIdx.x;
    const int j = threadIdx.x;
    const bool act = (j < 10);

    float w[10][4];
    float bz0 = 0.f, bz1 = 0.f, bz2 = 0.f, bz3 = 0.f;
#pragma unroll
    for (int p = 0; p < 10; ++p)
#pragma unroll
        for (int g = 0; g < 4; ++g)
            w[p][g] = act ? __ldg(Wh + p * 40 + g * 10 + j) : 0.f;
    if (act) {
        bz0 = __ldg(bias + j);
        bz1 = __ldg(bias + 10 + j);
        bz2 = __ldg(bias + 20 + j);
        bz3 = __ldg(bias + 30 + j);
    }

    float h = 0.f, c = 0.f;
    float4 z = make_float4(0.f, 0.f, 0.f, 0.f);
    if (act) {
        const float* zp = g_revxw + (size_t)b * 40;
        z = make_float4(__ldg(zp + j), __ldg(zp + 10 + j),
                        __ldg(zp + 20 + j), __ldg(zp + 30 + j));
    }

    for (int s = 0; s < T_; ++s) {
        float4 zn = make_float4(0.f, 0.f, 0.f, 0.f);
        if (act && s + 1 < T_) {
            const float* zp = g_revxw + ((size_t)(s + 1) * B_ + b) * 40;
            zn = make_float4(__ldg(zp + j), __ldg(zp + 10 + j),
                             __ldg(zp + 20 + j), __ldg(zp + 30 + j));
        }
        float zi = z.x + bz0, zf = z.y + bz1, zg = z.z + bz2, zo = z.w + bz3;
#pragma unroll
        for (int p = 0; p < 10; ++p) {
            float hp = __shfl_sync(0xffffffffu, h, p);
            zi = fmaf(hp, w[p][0], zi);
            zf = fmaf(hp, w[p][1], zf);
            zg = fmaf(hp, w[p][2], zg);
            zo = fmaf(hp, w[p][3], zo);
        }
        c = sigf(zf) * c + sigf(zi) * tanhf(zg);
        h = sigf(zo) * tanhf(c);
        if (act) g_fcore[((size_t)s * B_ + b) * 192 + 180 + j] = h;
        z = zn;
    }
}

// ------------------- gate MLP (+ h/barrier init folded in) -------------------
__global__ void __launch_bounds__(128) k_gate(const float* __restrict__ x,
        const float* __restrict__ d0W, const float* __restrict__ d0b,
        const float* __restrict__ d1W, const float* __restrict__ d1b,
        const float* __restrict__ gn)
{
    __shared__ float in_sh[8][448];
    __shared__ float hid_sh[8][100];
    const int q0 = blockIdx.x * 8;
    const int tid = threadIdx.x;

    if (blockIdx.x < 8) {
        float* hz = &g_h[0][blockIdx.x * 2048];
        for (int i = tid; i < 2048; i += 128) hz[i] = 0.f;
        if (blockIdx.x == 0 && tid == 0) { g_cnt = 0; g_gen = 0u; }
    }

    for (int i = tid; i < 8 * 448; i += 128) {
        int u = i / 448, e = i % 448;
        int q = q0 + u, t = q >> 5, b = q & 31;
        float v = 0.f;
        if (e < 190) { if (t < T_ - 1) v = g_fcore[((size_t)(t + 1) * B_ + b) * 192 + e]; }
        else if (e < 446) v = x[((size_t)b * T_ + t) * E_ + (e - 190)];
        in_sh[u][e] = v;
    }
    __syncthreads();
    if (tid < 100) {
        float acc[8];
#pragma unroll
        for (int u = 0; u < 8; ++u) acc[u] = d0b[tid];
        for (int e = 0; e < 446; ++e) {
            float w = d0W[(size_t)e * 100 + tid];
#pragma unroll
            for (int u = 0; u < 8; ++u) acc[u] = fmaf(in_sh[u][e], w, acc[u]);
        }
#pragma unroll
        for (int u = 0; u < 8; ++u) hid_sh[u][tid] = fmaxf(acc[u], 0.f);
    }
    __syncthreads();
    if (tid < 8) {
        const int u = tid, q = q0 + u, t = q >> 5, b = q & 31;
        float p0 = d1b[0], p1 = d1b[1];
        for (int j = 0; j < 100; ++j) {
            float hv = hid_sh[u][j];
            p0 = fmaf(hv, d1W[2 * j],     p0);
            p1 = fmaf(hv, d1W[2 * j + 1], p1);
        }
        float a0 = (p0 + gn[((size_t)t * B_ + b) * 2])     / 1e-5f;
        float a1 = (p1 + gn[((size_t)t * B_ + b) * 2 + 1]) / 1e-5f;
        float mx = fmaxf(a0, a1);
        float e0 = expf(a0 - mx), e1 = expf(a1 - mx);
        float s = e0 + e1;
        g_d[q] = make_float2(e0 / s, e1 / s);
    }
}

// ------------------- main persistent scan: R11 body, grid=152 (beats low-grid throttle) -------------------
__global__ void __launch_bounds__(256, 1) k_scan(const float* __restrict__ Wh,
                                                 float* __restrict__ out)
{
    extern __shared__ float sm[];
    float* h_sh    = sm;               // [32][512]  64KB
    float* part_sh = sm + 32 * 512;    // [8][512]   16KB
    const int tid  = threadIdx.x;
    const int nb   = blockIdx.x;

    // ---- barrier-only blocks (fill grid to >= SM count) ----
    if (nb >= NWORK) {
        if (tid == 0) {
            for (int t = 0; t < T_; ++t) {
                unsigned a = atom_add_release(&g_cnt, 1u);
                if (a == NBLK - 1) {
                    g_cnt = 0;
                    st_release(&g_gen, (unsigned)(t + 1));
                } else {
                    while (ld_acquire(&g_gen) < (unsigned)(t + 1)) __nanosleep(64);
                }
            }
        }
        return;
    }

    const int wid  = tid >> 5;
    const int lane = tid & 31;
    const int kc    = lane >> 4;
    const int c_idx = lane & 15;
    const int k0    = wid * 64 + kc * 32;
    const int ncol  = (c_idx >> 2) * 512 + nb * 4 + (c_idx & 3);
    const int rot   = nb & 3;

    u64 wreg[16];
#pragma unroll
    for (int j = 0; j < 16; ++j) {
        float w0 = __ldg(Wh + (size_t)(k0 + 2 * j)     * NG + ncol);
        float w1 = __ldg(Wh + (size_t)(k0 + 2 * j + 1) * NG + ncol);
        wreg[j] = pack2(w0, w1);
    }

    const int cb = tid >> 2;
    const int hh = tid & 3;
    const int hglob = nb * 4 + hh;
    float cst = 0.f;

    // prologue prefetch for t=0
    float4 zx = make_float4(0.f, 0.f, 0.f, 0.f);
    float2 dv = make_float2(0.f, 0.f);
    if (tid < 128) {
        const float* xw = g_xWx + ((size_t)cb) * NG + hglob;
        zx.x = __ldg(xw);
        zx.y = __ldg(xw + 512);
        zx.z = __ldg(xw + 1024);
        zx.w = __ldg(xw + 1536);
        dv = g_d[cb];
    }

    for (int t = 0; t < T_; ++t) {
        const int cur = t & 1;
        const float4* hg4 = (const float4*)g_h[cur];

        // stage chunk 0 (rotated by nb to de-hotspot L2)
        float4 pre[4];
        {
            const int base0 = rot * 1024 + tid;
#pragma unroll
            for (int q = 0; q < 4; ++q) pre[q] = __ldcg(hg4 + base0 + q * 256);
#pragma unroll
            for (int q = 0; q < 4; ++q) ((float4*)h_sh)[base0 + q * 256] = pre[q];
        }

        // prefetch NEXT step's xw/d
        float4 zxn; float2 dvn;
        if (tid < 128 && t + 1 < T_) {
            const float* xwn = g_xWx + ((size_t)(t + 1) * B_ + cb) * NG + hglob;
            zxn.x = __ldg(xwn);
            zxn.y = __ldg(xwn + 512);
            zxn.z = __ldg(xwn + 1024);
            zxn.w = __ldg(xwn + 1536);
            dvn = g_d[(t + 1) * B_ + cb];
        }
        __syncthreads();

        // ---- chunk-pipelined dot ----
        u64 acc2[32];
#pragma unroll
        for (int i = 0; i < 32; ++i) acc2[i] = 0ull;
#pragma unroll
        for (int cc = 0; cc < 4; ++cc) {
            const int ch = (cc + rot) & 3;
            if (cc < 3) {
                const int basen = (((cc + 1 + rot) & 3)) * 1024 + tid;
#pragma unroll
                for (int q = 0; q < 4; ++q) pre[q] = __ldcg(hg4 + basen + q * 256);
            }
            const float* hbase = h_sh + (ch * 8) * 512 + k0;
#pragma unroll
            for (int bb = 0; bb < 8; ++bb) {
                const ulonglong2* hp = (const ulonglong2*)(hbase + bb * 512);
                u64 a = acc2[cc * 8 + bb];
#pragma unroll
                for (int q = 0; q < 4; ++q) {
                    ulonglong2 h01 = hp[2 * q];
                    ulonglong2 h23 = hp[2 * q + 1];
                    a = ffma2(h01.x, wreg[4 * q + 0], a);
                    a = ffma2(h01.y, wreg[4 * q + 1], a);
                    a = ffma2(h23.x, wreg[4 * q + 2], a);
                    a = ffma2(h23.y, wreg[4 * q + 3], a);
                }
                acc2[cc * 8 + bb] = a;
            }
            if (cc < 3) {
                const int basen = (((cc + 1 + rot) & 3)) * 1024 + tid;
#pragma unroll
                for (int q = 0; q < 4; ++q) ((float4*)h_sh)[basen + q * 256] = pre[q];
                __syncthreads();
            }
        }

        // ---- reduce ----
#pragma unroll
        for (int idx = 0; idx < 32; ++idx) {
            float2 p = lohi(acc2[idx]);
            float v = p.x + p.y;
            v += __shfl_xor_sync(0xffffffffu, v, 16);
            if (kc == 0) {
                int realb = (((idx >> 3) + rot) & 3) * 8 + (idx & 7);
                part_sh[wid * 512 + realb * 16 + c_idx] = v;
            }
        }
        __syncthreads();

        if (tid < 128) {
            float zg4[4];
#pragma unroll
            for (int g = 0; g < 4; ++g) {
                float s = 0.f;
#pragma unroll
                for (int w8 = 0; w8 < 8; ++w8)
                    s += part_sh[w8 * 512 + cb * 16 + g * 4 + hh];
                zg4[g] = s;
            }
            float zi = zg4[0] + zx.x;
            float zf = zg4[1] + zx.y;
            float zg = zg4[2] + zx.z;
            float zo = zg4[3] + zx.w;
            float ccand = sigf(zf) * cst + sigf(zi) * tanhf(zg);
            float hcand = sigf(zo) * tanhf(ccand);
            float hold = h_sh[cb * 512 + hglob];
            float hnew = dv.x * hcand + dv.y * hold;
            cst = dv.x * ccand + dv.y * cst;
            g_h[1 - cur][cb * 512 + hglob] = hnew;
            out[(size_t)cb * (T_ * H_) + (size_t)t * H_ + hglob] = hcand;
            zx = zxn; dv = dvn;
        }
        __syncthreads();

        // ---- flat barrier: atomic release arrival + single-thread poll ----
        if (tid == 0) {
            unsigned a = atom_add_release(&g_cnt, 1u);
            if (a == NBLK - 1) {
                g_cnt = 0;
                st_release(&g_gen, (unsigned)(t + 1));
            } else {
                while (ld_acquire(&g_gen) < (unsigned)(t + 1)) __nanosleep(16);
            }
        }
        __syncthreads();
    }
}

extern "C" void kernel_launch(void* const* d_in, const int* in_sizes, int n_in,
                              void* d_out, int out_size) {
    const float* x   = (const float*)d_in[0];
    const float* c1w = (const float*)d_in[1];
    const float* c1b = (const float*)d_in[2];
    const float* c2w = (const float*)d_in[3];
    const float* c2b = (const float*)d_in[4];
    const float* c3w = (const float*)d_in[5];
    const float* c3b = (const float*)d_in[6];
    const float* rWx = (const float*)d_in[7];
    const float* rWh = (const float*)d_in[8];
    const float* rb  = (const float*)d_in[9];
    const float* d0W = (const float*)d_in[10];
    const float* d0b = (const float*)d_in[11];
    const float* d1W = (const float*)d_in[12];
    const float* d1b = (const float*)d_in[13];
    const float* cWx = (const float*)d_in[14];
    const float* cWh = (const float*)d_in[15];
    const float* cb  = (const float*)d_in[16];
    const float* gn  = (const float*)d_in[17];
    float* out = (float*)d_out;

    static int smem_set = 0;
    const int SMEM = (32 * 512 + 8 * 512) * 4;   // 80 KB
    if (!smem_set) {
        cudaFuncSetAttribute(k_scan, cudaFuncAttributeMaxDynamicSharedMemorySize, SMEM);
        smem_set = 1;
    }

    k_pre<<<3584, 256>>>(x, cWx, cb, c1w, c1b, c2w, c2b, c3w, c3b, rWx);
    k_revscan<<<32, 32>>>(rWh, rb);
    k_gate<<<(T_ * B_) / 8, 128>>>(x, d0W, d0b, d1W, d1b, gn);
    k_scan<<<NBLK, 256, SMEM>>>(cWh, out);
}

// round 17
// speedup vs baseline: 1.2573x; 1.0257x over previous
#include <cuda_runtime.h>
#include <math.h>
#include <stdint.h>

#define B_   32
#define T_   512
#define E_   256
#define H_   512
#define NG   2048
#define NWORK 128
#define NBLK  152

typedef unsigned long long u64;

__device__ __align__(16) float  g_xWx  [(size_t)T_ * B_ * NG];
__device__ __align__(16) float  g_fcore[(size_t)T_ * B_ * 192];
__device__ __align__(16) float  g_revxw[(size_t)T_ * B_ * 40];
__device__ __align__(16) float2 g_d    [T_ * B_];
__device__ __align__(16) float  g_h    [2][B_ * H_];
__device__ unsigned g_cnt;
__device__ unsigned g_gen;

__device__ __forceinline__ float sigf(float x) { return 1.f / (1.f + expf(-x)); }

// ---- packed f32x2 helpers ----
__device__ __forceinline__ u64 ffma2(u64 a, u64 b, u64 c) {
    u64 d;
    asm("fma.rn.f32x2 %0, %1, %2, %3;" : "=l"(d) : "l"(a), "l"(b), "l"(c));
    return d;
}
__device__ __forceinline__ u64 dup2(float x) {
    u64 r; asm("mov.b64 %0, {%1, %1};" : "=l"(r) : "f"(x)); return r;
}
__device__ __forceinline__ u64 pack2(float lo, float hi) {
    u64 r; asm("mov.b64 %0, {%1, %2};" : "=l"(r) : "f"(lo), "f"(hi)); return r;
}
__device__ __forceinline__ float2 lohi(u64 v) {
    float2 r; asm("mov.b64 {%0, %1}, %2;" : "=f"(r.x), "=f"(r.y) : "l"(v)); return r;
}

// ---- release/acquire primitives ----
__device__ __forceinline__ unsigned atom_add_release(unsigned* p, unsigned v) {
    unsigned old;
    asm volatile("atom.release.gpu.global.add.u32 %0, [%1], %2;"
                 : "=r"(old) : "l"(p), "r"(v) : "memory");
    return old;
}
__device__ __forceinline__ void st_release(unsigned* p, unsigned v) {
    asm volatile("st.release.gpu.global.u32 [%0], %1;" :: "l"(p), "r"(v) : "memory");
}
__device__ __forceinline__ unsigned ld_acquire(const unsigned* p) {
    unsigned v;
    asm volatile("ld.acquire.gpu.global.u32 %0, [%1];" : "=r"(v) : "l"(p) : "memory");
    return v;
}

// =================== fused pre-kernel: xwx (2048) | conv (1024) | revxw (512) ===================
__global__ void __launch_bounds__(256) k_pre(const float* __restrict__ x,
        const float* __restrict__ cWx, const float* __restrict__ cbias,
        const float* __restrict__ w1, const float* __restrict__ b1,
        const float* __restrict__ w2, const float* __restrict__ b2,
        const float* __restrict__ w3, const float* __restrict__ b3,
        const float* __restrict__ rWx)
{
    __shared__ __align__(16) float buf[8192];
    const int bid = blockIdx.x;
    const int tid = threadIdx.x;

    if (bid < 2048) {
        // ---------- xWx GEMM ----------
        float (*a_sh)[128] = (float(*)[128])buf;
        float (*b_sh)[128] = (float(*)[128])(buf + 1024);
        const int n0 = (bid & 15) * 128;
        const int m0 = (bid >> 4) * 128;
        const int ty8 = (tid >> 4) * 8;
        const int tx8 = (tid & 15) * 8;

        u64 acc[8][4];
#pragma unroll
        for (int i = 0; i < 8; ++i)
#pragma unroll
            for (int j = 0; j < 4; ++j) acc[i][j] = 0ull;

        const int arow = tid >> 1;
        const int akq  = (tid & 1) * 4;
        const int m    = m0 + arow;
        const int bb   = m & 31;
        const int tt   = m >> 5;
        const float* aptr = x + ((size_t)bb * T_ + tt) * E_ + akq;
        const int bkk = tid >> 5;
        const int bnq = (tid & 31) * 4;

        for (int k0 = 0; k0 < E_; k0 += 8) {
            float4 av = *(const float4*)(aptr + k0);
            a_sh[akq + 0][arow] = av.x;
            a_sh[akq + 1][arow] = av.y;
            a_sh[akq + 2][arow] = av.z;
            a_sh[akq + 3][arow] = av.w;
            *(float4*)&b_sh[bkk][bnq] = *(const float4*)(cWx + (size_t)(k0 + bkk) * NG + n0 + bnq);
            __syncthreads();
#pragma unroll
            for (int k = 0; k < 8; ++k) {
                float af[8];
                *(float4*)(af)     = *(const float4*)&a_sh[k][ty8];
                *(float4*)(af + 4) = *(const float4*)&a_sh[k][ty8 + 4];
                ulonglong2 b01 = *(const ulonglong2*)&b_sh[k][tx8];
                ulonglong2 b23 = *(const ulonglong2*)&b_sh[k][tx8 + 4];
#pragma unroll
                for (int i = 0; i < 8; ++i) {
                    u64 ai = dup2(af[i]);
                    acc[i][0] = ffma2(ai, b01.x, acc[i][0]);
                    acc[i][1] = ffma2(ai, b01.y, acc[i][1]);
                    acc[i][2] = ffma2(ai, b23.x, acc[i][2]);
                    acc[i][3] = ffma2(ai, b23.y, acc[i][3]);
                }
            }
            __syncthreads();
        }
        float bsv[8];
        *(float4*)(bsv)     = *(const float4*)(cbias + n0 + tx8);
        *(float4*)(bsv + 4) = *(const float4*)(cbias + n0 + tx8 + 4);
#pragma unroll
        for (int i = 0; i < 8; ++i) {
            float* cp = g_xWx + (size_t)(m0 + ty8 + i) * NG + n0 + tx8;
            float2 p0 = lohi(acc[i][0]), p1 = lohi(acc[i][1]);
            float2 p2 = lohi(acc[i][2]), p3 = lohi(acc[i][3]);
            *(float4*)cp       = make_float4(p0.x + bsv[0], p0.y + bsv[1], p1.x + bsv[2], p1.y + bsv[3]);
            *(float4*)(cp + 4) = make_float4(p2.x + bsv[4], p2.y + bsv[5], p3.x + bsv[6], p3.y + bsv[7]);
        }
    } else if (bid < 3072) {
        // ---------- convs: 16 timesteps per block, 4 t per thread ----------
        float (*xs)[256] = (float(*)[256])buf;
        const int cb = bid - 2048;
        const int t0 = (cb & 31) * 16;
        const int b  = cb >> 5;

        for (int i = tid; i < 20 * 256; i += 256) {
            int r = i >> 8, e = i & 255;
            int t = t0 - 2 + r;
            xs[r][e] = (t >= 0 && t < T_) ? x[((size_t)b * T_ + t) * E_ + e] : 0.f;
        }
        __syncthreads();
        if (tid >= 180) return;

        const int tq  = tid / 45;
        const int grp = tid % 45;
        const float* w; const float* bias; int K, pl, cbase, c4;
        if (grp < 15)      { w = w1; bias = b1; K = 3; pl = 1; cbase = 0;   c4 = grp * 4; }
        else if (grp < 30) { w = w2; bias = b2; K = 4; pl = 1; cbase = 60;  c4 = (grp - 15) * 4; }
        else               { w = w3; bias = b3; K = 5; pl = 2; cbase = 120; c4 = (grp - 30) * 4; }

        u64 a01[4], a23[4];
        u64 bi01 = pack2(bias[c4], bias[c4 + 1]);
        u64 bi23 = pack2(bias[c4 + 2], bias[c4 + 3]);
#pragma unroll
        for (int i = 0; i < 4; ++i) { a01[i] = bi01; a23[i] = bi23; }

        for (int dt = 0; dt < K; ++dt) {
            const int rb = tq * 4 + dt - pl + 2;
            const float* wp = w + (size_t)dt * E_ * 60 + c4;
#pragma unroll 2
            for (int e = 0; e < E_; ++e) {
                ulonglong2 wv = *(const ulonglong2*)(wp + (size_t)e * 60);
#pragma unroll
                for (int i = 0; i < 4; ++i) {
                    u64 xd = dup2(xs[rb + i][e]);
                    a01[i] = ffma2(xd, wv.x, a01[i]);
                    a23[i] = ffma2(xd, wv.y, a23[i]);
                }
            }
        }
#pragma unroll
        for (int i = 0; i < 4; ++i) {
            const int t = t0 + tq * 4 + i;
            float2 p0 = lohi(a01[i]), p1 = lohi(a23[i]);
            *(float4*)&g_fcore[((size_t)t * B_ + b) * 192 + cbase + c4] =
                make_float4(p0.x, p0.y, p1.x, p1.y);
        }
    } else {
        // ---------- rev-LSTM input projection ----------
        float (*xr)[256] = (float(*)[256])buf;
        const int s = bid - 3072;
        const int t = T_ - 1 - s;
        for (int i = tid; i < 32 * 256; i += 256) {
            int b = i >> 8, e = i & 255;
            xr[b][e] = x[((size_t)b * T_ + t) * E_ + e];
        }
        __syncthreads();
#pragma unroll
        for (int pass = 0; pass < 2; ++pass) {
            int jj = tid + pass * 256;
            if (jj >= 320) break;
            const int b = jj / 10, j = jj % 10;
            float a0 = 0.f, a1 = 0.f, a2 = 0.f, a3 = 0.f;
#pragma unroll 4
            for (int e = 0; e < 256; ++e) {
                float xv = xr[b][e];
                const float* wp = rWx + (size_t)e * 40 + j;
                a0 = fmaf(xv, __ldg(wp),      a0);
                a1 = fmaf(xv, __ldg(wp + 10), a1);
                a2 = fmaf(xv, __ldg(wp + 20), a2);
                a3 = fmaf(xv, __ldg(wp + 30), a3);
            }
            float* dst = &g_revxw[((size_t)s * B_ + b) * 40 + j];
            dst[0] = a0; dst[10] = a1; dst[20] = a2; dst[30] = a3;
        }
    }
}

// ------------------- rev-LSTM scan: 32 independent warps, shfl exchange -------------------
__global__ void __launch_bounds__(32) k_revscan(const float* __restrict__ Wh,
                                                const float* __restrict__ bias)
{
    const int b = blockIdx.x;
    const int j = threadIdx.x;
    const bool act = (j < 10);

    float w[10][4];
    float bz0 = 0.f, bz1 = 0.f, bz2 = 0.f, bz3 = 0.f;
#pragma unroll
    for (int p = 0; p < 10; ++p)
#pragma unroll
        for (int g = 0; g < 4; ++g)
            w[p][g] = act ? __ldg(Wh + p * 40 + g * 10 + j) : 0.f;
    if (act) {
        bz0 = __ldg(bias + j);
        bz1 = __ldg(bias + 10 + j);
        bz2 = __ldg(bias + 20 + j);
        bz3 = __ldg(bias + 30 + j);
    }

    float h = 0.f, c = 0.f;
    float4 z = make_float4(0.f, 0.f, 0.f, 0.f);
    if (act) {
        const float* zp = g_revxw + (size_t)b * 40;
        z = make_float4(__ldg(zp + j), __ldg(zp + 10 + j),
                        __ldg(zp + 20 + j), __ldg(zp + 30 + j));
    }

    for (int s = 0; s < T_; ++s) {
        float4 zn = make_float4(0.f, 0.f, 0.f, 0.f);
        if (act && s + 1 < T_) {
            const float* zp = g_revxw + ((size_t)(s + 1) * B_ + b) * 40;
            zn = make_float4(__ldg(zp + j), __ldg(zp + 10 + j),
                             __ldg(zp + 20 + j), __ldg(zp + 30 + j));
        }
        float zi = z.x + bz0, zf = z.y + bz1, zg = z.z + bz2, zo = z.w + bz3;
#pragma unroll
        for (int p = 0; p < 10; ++p) {
            float hp = __shfl_sync(0xffffffffu, h, p);
            zi = fmaf(hp, w[p][0], zi);
            zf = fmaf(hp, w[p][1], zf);
            zg = fmaf(hp, w[p][2], zg);
            zo = fmaf(hp, w[p][3], zo);
        }
        c = sigf(zf) * c + sigf(zi) * tanhf(zg);
        h = sigf(zo) * tanhf(c);
        if (act) g_fcore[((size_t)s * B_ + b) * 192 + 180 + j] = h;
        z = zn;
    }
}

// ------------------- gate MLP (+ h/barrier init folded in) -------------------
__global__ void __launch_bounds__(128) k_gate(const float* __restrict__ x,
        const float* __restrict__ d0W, const float* __restrict__ d0b,
        const float* __restrict__ d1W, const float* __restrict__ d1b,
        const float* __restrict__ gn)
{
    __shared__ float in_sh[8][448];
    __shared__ float hid_sh[8][100];
    const int q0 = blockIdx.x * 8;
    const int tid = threadIdx.x;

    if (blockIdx.x < 8) {
        float* hz = &g_h[0][blockIdx.x * 2048];
        for (int i = tid; i < 2048; i += 128) hz[i] = 0.f;
        if (blockIdx.x == 0 && tid == 0) { g_cnt = 0; g_gen = 0u; }
    }

    for (int i = tid; i < 8 * 448; i += 128) {
        int u = i / 448, e = i % 448;
        int q = q0 + u, t = q >> 5, b = q & 31;
        float v = 0.f;
        if (e < 190) { if (t < T_ - 1) v = g_fcore[((size_t)(t + 1) * B_ + b) * 192 + e]; }
        else if (e < 446) v = x[((size_t)b * T_ + t) * E_ + (e - 190)];
        in_sh[u][e] = v;
    }
    __syncthreads();
    if (tid < 100) {
        float acc[8];
#pragma unroll
        for (int u = 0; u < 8; ++u) acc[u] = d0b[tid];
        for (int e = 0; e < 446; ++e) {
            float w = d0W[(size_t)e * 100 + tid];
#pragma unroll
            for (int u = 0; u < 8; ++u) acc[u] = fmaf(in_sh[u][e], w, acc[u]);
        }
#pragma unroll
        for (int u = 0; u < 8; ++u) hid_sh[u][tid] = fmaxf(acc[u], 0.f);
    }
    __syncthreads();
    if (tid < 8) {
        const int u = tid, q = q0 + u, t = q >> 5, b = q & 31;
        float p0 = d1b[0], p1 = d1b[1];
        for (int j = 0; j < 100; ++j) {
            float hv = hid_sh[u][j];
            p0 = fmaf(hv, d1W[2 * j],     p0);
            p1 = fmaf(hv, d1W[2 * j + 1], p1);
        }
        float a0 = (p0 + gn[((size_t)t * B_ + b) * 2])     / 1e-5f;
        float a1 = (p1 + gn[((size_t)t * B_ + b) * 2 + 1]) / 1e-5f;
        float mx = fmaxf(a0, a1);
        float e0 = expf(a0 - mx), e1 = expf(a1 - mx);
        float s = e0 + e1;
        g_d[q] = make_float2(e0 / s, e1 / s);
    }
}

// ------------------- main persistent scan: 512 threads (16 warps) for latency hiding -------------------
// Warp wid: kw = wid&7 -> k window [kw*64,(kw+1)*64); bg = wid>>3 -> batches [bg*16,(bg+1)*16)
// Lane: kc = lane>>4 (k half, 32 floats), c_idx = lane&15 (output column)
__global__ void __launch_bounds__(512, 1) k_scan(const float* __restrict__ Wh,
                                                 float* __restrict__ out)
{
    extern __shared__ float sm[];
    float* h_sh    = sm;               // [32][512]  64KB
    float* part_sh = sm + 32 * 512;    // [8][512]   16KB
    const int tid  = threadIdx.x;
    const int nb   = blockIdx.x;

    // ---- barrier-only blocks (fill grid to >= SM count) ----
    if (nb >= NWORK) {
        if (tid == 0) {
            for (int t = 0; t < T_; ++t) {
                unsigned a = atom_add_release(&g_cnt, 1u);
                if (a == NBLK - 1) {
                    g_cnt = 0;
                    st_release(&g_gen, (unsigned)(t + 1));
                } else {
                    while (ld_acquire(&g_gen) < (unsigned)(t + 1)) __nanosleep(64);
                }
            }
        }
        return;
    }

    const int wid  = tid >> 5;
    const int lane = tid & 31;
    const int kw   = wid & 7;
    const int bg   = wid >> 3;          // 0 or 1 -> batch group of 16
    const int kc    = lane >> 4;
    const int c_idx = lane & 15;
    const int k0    = kw * 64 + kc * 32;
    const int ncol  = (c_idx >> 2) * 512 + nb * 4 + (c_idx & 3);

    u64 wreg[16];
#pragma unroll
    for (int j = 0; j < 16; ++j) {
        float w0 = __ldg(Wh + (size_t)(k0 + 2 * j)     * NG + ncol);
        float w1 = __ldg(Wh + (size_t)(k0 + 2 * j + 1) * NG + ncol);
        wreg[j] = pack2(w0, w1);
    }

    const int cb = tid >> 2;            // combine thread batch (tid<128)
    const int hh = tid & 3;
    const int hglob = nb * 4 + hh;
    float cst = 0.f;

    // prologue prefetch for t=0
    float4 zx = make_float4(0.f, 0.f, 0.f, 0.f);
    float2 dv = make_float2(0.f, 0.f);
    if (tid < 128) {
        const float* xw = g_xWx + ((size_t)cb) * NG + hglob;
        zx.x = __ldg(xw);
        zx.y = __ldg(xw + 512);
        zx.z = __ldg(xw + 1024);
        zx.w = __ldg(xw + 1536);
        dv = g_d[cb];
    }

    for (int t = 0; t < T_; ++t) {
        const int cur = t & 1;
        const float4* hg4 = (const float4*)g_h[cur];

        // single-shot h staging: 8 independent float4 loads per thread (MLP=8)
        float4 pre[8];
#pragma unroll
        for (int q = 0; q < 8; ++q) pre[q] = __ldcg(hg4 + tid + q * 512);

        // prefetch NEXT step's xw/d (consumed after next barrier)
        float4 zxn; float2 dvn;
        if (tid < 128 && t + 1 < T_) {
            const float* xwn = g_xWx + ((size_t)(t + 1) * B_ + cb) * NG + hglob;
            zxn.x = __ldg(xwn);
            zxn.y = __ldg(xwn + 512);
            zxn.z = __ldg(xwn + 1024);
            zxn.w = __ldg(xwn + 1536);
            dvn = g_d[(t + 1) * B_ + cb];
        }
#pragma unroll
        for (int q = 0; q < 8; ++q) ((float4*)h_sh)[tid + q * 512] = pre[q];
        __syncthreads();

        // ---- dot: 16 batches x 32 k per thread ----
        u64 acc2[16];
#pragma unroll
        for (int i = 0; i < 16; ++i) acc2[i] = 0ull;
        const float* hbase = h_sh + (bg * 16) * 512 + k0;
#pragma unroll
        for (int bb = 0; bb < 16; ++bb) {
            const ulonglong2* hp = (const ulonglong2*)(hbase + bb * 512);
            u64 a = acc2[bb];
#pragma unroll
            for (int q = 0; q < 4; ++q) {
                ulonglong2 h01 = hp[2 * q];
                ulonglong2 h23 = hp[2 * q + 1];
                a = ffma2(h01.x, wreg[4 * q + 0], a);
                a = ffma2(h01.y, wreg[4 * q + 1], a);
                a = ffma2(h23.x, wreg[4 * q + 2], a);
                a = ffma2(h23.y, wreg[4 * q + 3], a);
            }
            acc2[bb] = a;
        }

        // ---- reduce: f32x2 collapse + shfl (kc pair) -> part_sh ----
#pragma unroll
        for (int i = 0; i < 16; ++i) {
            float2 p = lohi(acc2[i]);
            float v = p.x + p.y;
            v += __shfl_xor_sync(0xffffffffu, v, 16);
            if (kc == 0)
                part_sh[kw * 512 + (bg * 16 + i) * 16 + c_idx] = v;
        }
        __syncthreads();

        if (tid < 128) {
            float zg4[4];
#pragma unroll
            for (int g = 0; g < 4; ++g) {
                float s = 0.f;
#pragma unroll
                for (int w8 = 0; w8 < 8; ++w8)
                    s += part_sh[w8 * 512 + cb * 16 + g * 4 + hh];
                zg4[g] = s;
            }
            float zi = zg4[0] + zx.x;
            float zf = zg4[1] + zx.y;
            float zg = zg4[2] + zx.z;
            float zo = zg4[3] + zx.w;
            float ccand = sigf(zf) * cst + sigf(zi) * tanhf(zg);
            float hcand = sigf(zo) * tanhf(ccand);
            float hold = h_sh[cb * 512 + hglob];
            float hnew = dv.x * hcand + dv.y * hold;
            cst = dv.x * ccand + dv.y * cst;
            g_h[1 - cur][cb * 512 + hglob] = hnew;
            out[(size_t)cb * (T_ * H_) + (size_t)t * H_ + hglob] = hcand;
            zx = zxn; dv = dvn;
        }
        __syncthreads();

        // ---- flat barrier: atomic release arrival + single-thread poll ----
        if (tid == 0) {
            unsigned a = atom_add_release(&g_cnt, 1u);
            if (a == NBLK - 1) {
                g_cnt = 0;
                st_release(&g_gen, (unsigned)(t + 1));
            } else {
                while (ld_acquire(&g_gen) < (unsigned)(t + 1)) __nanosleep(16);
            }
        }
        __syncthreads();
    }
}

extern "C" void kernel_launch(void* const* d_in, const int* in_sizes, int n_in,
                              void* d_out, int out_size) {
    const float* x   = (const float*)d_in[0];
    const float* c1w = (const float*)d_in[1];
    const float* c1b = (const float*)d_in[2];
    const float* c2w = (const float*)d_in[3];
    const float* c2b = (const float*)d_in[4];
    const float* c3w = (const float*)d_in[5];
    const float* c3b = (const float*)d_in[6];
    const float* rWx = (const float*)d_in[7];
    const float* rWh = (const float*)d_in[8];
    const float* rb  = (const float*)d_in[9];
    const float* d0W = (const float*)d_in[10];
    const float* d0b = (const float*)d_in[11];
    const float* d1W = (const float*)d_in[12];
    const float* d1b = (const float*)d_in[13];
    const float* cWx = (const float*)d_in[14];
    const float* cWh = (const float*)d_in[15];
    const float* cb  = (const float*)d_in[16];
    const float* gn  = (const float*)d_in[17];
    float* out = (float*)d_out;

    static int smem_set = 0;
    const int SMEM = (32 * 512 + 8 * 512) * 4;   // 80 KB
    if (!smem_set) {
        cudaFuncSetAttribute(k_scan, cudaFuncAttributeMaxDynamicSharedMemorySize, SMEM);
        smem_set = 1;
    }

    k_pre<<<3584, 256>>>(x, cWx, cb, c1w, c1b, c2w, c2b, c3w, c3b, rWx);
    k_revscan<<<32, 32>>>(rWh, rb);
    k_gate<<<(T_ * B_) / 8, 128>>>(x, d0W, d0b, d1W, d1b, gn);
    k_scan<<<NBLK, 512, SMEM>>>(cWh, out);
}